// round 8
// baseline (speedup 1.0000x reference)
#include <cuda_runtime.h>
#include <math.h>

#define AMAX   76725
#define NCLS   80
#define KTOP   1000
#define NCAND  2048
#define NWORDS 16
#define NBINS  8192
#define THR_SEL 0.98f
#define NPH    37          // mask row-phases: 80*37=2960 blocks = 5 exact waves @4/SM

__device__ float4              g_boxes[AMAX];
__device__ unsigned long long  g_cand[NCLS * NCAND];
__device__ int                 g_cnt[NCLS];
__device__ float               g_scoreK[NCLS * KTOP];
__device__ float4              g_boxK[NCLS * KTOP];
__device__ float               g_areaK[NCLS * KTOP];
__device__ unsigned long long  g_alive[NCLS * NWORDS];
__device__ unsigned long long  g_mask[NCLS * KTOP * NWORDS]; // words wb<i>>6 never written/read

// ---------------------------------------------------------------------------
__device__ __forceinline__ unsigned fkey(float s) {
    unsigned b = __float_as_uint(s);
    return (b & 0x80000000u) ? ~b : (b | 0x80000000u);
}
__device__ __forceinline__ float fkey_inv(unsigned k) {
    return __uint_as_float((k & 0x80000000u) ? (k & 0x7FFFFFFFu) : ~k);
}
__device__ __forceinline__ unsigned long long mkkey(float s, unsigned a) {
    return ((unsigned long long)fkey(s) << 32) |
           (unsigned long long)(0xFFFFFFFFu - a);
}

// ---------------------------------------------------------------------------
// Kernel 1: decode + clip all boxes; zero per-class counters.
// ---------------------------------------------------------------------------
__global__ void decode_kernel(const float* __restrict__ reg,
                              const float* __restrict__ anch,
                              int A, float W, float H) {
    int a = blockIdx.x * blockDim.x + threadIdx.x;
    if (a < NCLS) g_cnt[a] = 0;
    if (a >= A) return;
    float4 an = reinterpret_cast<const float4*>(anch)[a];
    float4 dl = reinterpret_cast<const float4*>(reg)[a];
    float aw = an.z - an.x;
    float ah = an.w - an.y;
    float cx = an.x + 0.5f * aw;
    float cy = an.y + 0.5f * ah;
    float pcx = cx + dl.x * 0.1f * aw;
    float pcy = cy + dl.y * 0.1f * ah;
    float pw = expf(dl.z * 0.2f) * aw;
    float ph = expf(dl.w * 0.2f) * ah;
    float4 b;
    b.x = fmaxf(pcx - 0.5f * pw, 0.0f);
    b.y = fmaxf(pcy - 0.5f * ph, 0.0f);
    b.z = fminf(pcx + 0.5f * pw, W);
    b.w = fminf(pcy + 0.5f * ph, H);
    g_boxes[a] = b;
}

// ---------------------------------------------------------------------------
// Kernel 2: coalesced single-pass candidate selection, fixed threshold.
// ---------------------------------------------------------------------------
__global__ __launch_bounds__(320)
void select_kernel(const float* __restrict__ cls, int A, int C, int astep) {
    int gthreads = gridDim.x * blockDim.x;
    int t = blockIdx.x * blockDim.x + threadIdx.x;
    int nf4 = (A * C) >> 2;
    const float4* cls4 = reinterpret_cast<const float4*>(cls);
    int e0 = t << 2;
    int a  = e0 / C;
    int c0 = e0 - a * C;
    for (int f = t; f < nf4; f += gthreads, a += astep) {
        float4 v = cls4[f];
        if (v.x > THR_SEL) {
            int p = atomicAdd(&g_cnt[c0 + 0], 1);
            if (p < NCAND) g_cand[(c0 + 0) * NCAND + p] = mkkey(v.x, (unsigned)a);
        }
        if (v.y > THR_SEL) {
            int p = atomicAdd(&g_cnt[c0 + 1], 1);
            if (p < NCAND) g_cand[(c0 + 1) * NCAND + p] = mkkey(v.y, (unsigned)a);
        }
        if (v.z > THR_SEL) {
            int p = atomicAdd(&g_cnt[c0 + 2], 1);
            if (p < NCAND) g_cand[(c0 + 2) * NCAND + p] = mkkey(v.z, (unsigned)a);
        }
        if (v.w > THR_SEL) {
            int p = atomicAdd(&g_cnt[c0 + 3], 1);
            if (p < NCAND) g_cand[(c0 + 3) * NCAND + p] = mkkey(v.w, (unsigned)a);
        }
    }
}

// ---------------------------------------------------------------------------
// Kernel 3: per-class sort (+embedded exact-reselect guard), extract top-K.
// ---------------------------------------------------------------------------
__global__ __launch_bounds__(1024)
void sort_kernel(const float* __restrict__ cls, int A, int C) {
    __shared__ unsigned long long buf[4096];       // 32 KB: cand = buf[0..2047]
    __shared__ unsigned long long salive[NWORDS];
    __shared__ int sT, sCnt;
    unsigned long long* cand = buf;
    unsigned*           hist = (unsigned*)buf;

    int c = blockIdx.x, tid = threadIdx.x;
    int n = g_cnt[c];
    bool bad = (n < KTOP) | (n > NCAND);

    if (!bad) {
        for (int i = tid; i < NCAND; i += 1024)
            cand[i] = (i < n) ? g_cand[c * NCAND + i] : 0ull;
        __syncthreads();
    } else {
        for (int i = tid; i < NBINS; i += 1024) hist[i] = 0u;
        if (tid == 0) sCnt = 0;
        __syncthreads();
        for (int a = tid; a < A; a += 1024) {
            float s = cls[a * C + c];
            int b = (int)(s * (float)NBINS);
            b = max(0, min(NBINS - 1, b));
            atomicAdd(&hist[b], 1u);
        }
        __syncthreads();
        if (tid == 0) {
            int cum = 0, t;
            for (t = NBINS - 1; t >= 0; t--) {
                cum += (int)hist[t];
                if (cum >= KTOP) break;
            }
            sT = (t < 0) ? 0 : t;
        }
        __syncthreads();
        int T = sT;
        unsigned long long keys[8]; int nk = 0;
        for (int a = tid; a < A; a += 1024) {
            float s = cls[a * C + c];
            int b = (int)(s * (float)NBINS);
            b = max(0, min(NBINS - 1, b));
            if (b >= T && nk < 8) keys[nk++] = mkkey(s, (unsigned)a);
        }
        __syncthreads();
        for (int q = 0; q < nk; q++) {
            int p = atomicAdd(&sCnt, 1);
            if (p < NCAND) cand[p] = keys[q];
        }
        __syncthreads();
        n = min(sCnt, NCAND);
        for (int i = tid; i < NCAND; i += 1024)
            if (i >= n) cand[i] = 0ull;
        __syncthreads();
    }

    for (int k = 2; k <= NCAND; k <<= 1) {
        for (int j = k >> 1; j > 0; j >>= 1) {
            #pragma unroll
            for (int rep = 0; rep < 2; rep++) {
                int i = tid + rep * 1024;
                int ixj = i ^ j;
                if (ixj > i) {
                    unsigned long long a0 = cand[i], b0 = cand[ixj];
                    bool desc = ((i & k) == 0);
                    bool swap = desc ? (a0 < b0) : (a0 > b0);
                    if (swap) { cand[i] = b0; cand[ixj] = a0; }
                }
            }
            __syncthreads();
        }
    }

    bool alive = false;
    {
        unsigned long long v = cand[min(tid, NCAND - 1)];
        float s = fkey_inv((unsigned)(v >> 32));
        unsigned a = 0xFFFFFFFFu - (unsigned)(v & 0xFFFFFFFFull);
        bool valid = (a < (unsigned)A);
        float4 bb = valid ? g_boxes[min(a, (unsigned)(AMAX - 1))]
                          : make_float4(0.f, 0.f, 0.f, 0.f);
        if (!valid) s = 0.f;
        if (tid < KTOP) {
            int o = c * KTOP + tid;
            g_scoreK[o] = s;
            g_boxK[o]   = bb;
            g_areaK[o]  = (bb.z - bb.x) * (bb.w - bb.y);
            alive = (s > 0.001f);
        }
    }
    unsigned bal = __ballot_sync(0xFFFFFFFFu, alive);
    if ((tid & 63) == 0 && tid < KTOP + 63)
        salive[tid >> 6] = (unsigned long long)bal;
    __syncthreads();
    if ((tid & 63) == 32 && tid < KTOP + 63)
        atomicOr(&salive[tid >> 6], (unsigned long long)bal << 32);
    __syncthreads();
    if (tid < NWORDS) g_alive[c * NWORDS + tid] = salive[tid];
}

// ---------------------------------------------------------------------------
// Kernel 4: IoU suppression bitmask. Grid (C, 37): 2960 equal blocks = 5 exact
// waves @ 4 blocks/SM. No smem; j-boxes in registers, i-box uniform LDG with
// depth-1 prefetch. IoU expressions token-identical to the passing kernel.
// ---------------------------------------------------------------------------
__global__ __launch_bounds__(512)
void mask_kernel() {
    int c = blockIdx.x, ph = blockIdx.y, tid = threadIdx.x;
    int warp = tid >> 5, lane = tid & 31;
    int wb = warp;
    int j1 = wb * 64 + lane;
    int j2 = j1 + 32;
    const float4* __restrict__ boxK  = g_boxK  + (size_t)c * KTOP;
    const float*  __restrict__ areaK = g_areaK + (size_t)c * KTOP;

    float4 B1 = (j1 < KTOP) ? boxK[j1] : make_float4(3e8f, 3e8f, 3e8f, 3e8f);
    float ar1 = (j1 < KTOP) ? areaK[j1] : 0.f;
    float4 B2 = (j2 < KTOP) ? boxK[j2] : make_float4(3e8f, 3e8f, 3e8f, 3e8f);
    float ar2 = (j2 < KTOP) ? areaK[j2] : 0.f;

    int iLim = wb * 64 + 64;
    if (iLim > KTOP) iLim = KTOP;
    unsigned long long* mrow = g_mask + (size_t)c * KTOP * NWORDS + wb;

    int i = ph;
    float4 BI; float ai;
    if (i < iLim) { BI = boxK[i]; ai = areaK[i]; }
    while (i < iLim) {
        int inxt = i + NPH;
        float4 BN; float an;
        if (inxt < iLim) { BN = boxK[inxt]; an = areaK[inxt]; }  // prefetch

        float xx1 = fmaxf(BI.x, B1.x), yy1 = fmaxf(BI.y, B1.y);
        float xx2 = fminf(BI.z, B1.z), yy2 = fminf(BI.w, B1.w);
        float inter = fmaxf(xx2 - xx1, 0.f) * fmaxf(yy2 - yy1, 0.f);
        bool p1 = (j1 > i) && (inter > 0.5f * (ai + ar1 - inter + 1e-8f));
        xx1 = fmaxf(BI.x, B2.x); yy1 = fmaxf(BI.y, B2.y);
        xx2 = fminf(BI.z, B2.z); yy2 = fminf(BI.w, B2.w);
        inter = fmaxf(xx2 - xx1, 0.f) * fmaxf(yy2 - yy1, 0.f);
        bool p2 = (j2 > i) && (inter > 0.5f * (ai + ar2 - inter + 1e-8f));

        unsigned m1 = __ballot_sync(0xFFFFFFFFu, p1);
        unsigned m2 = __ballot_sync(0xFFFFFFFFu, p2);
        if (lane == 0)
            mrow[(size_t)i * NWORDS] = ((unsigned long long)m2 << 32) | m1;

        BI = BN; ai = an; i = inxt;
    }
}

// ---------------------------------------------------------------------------
// Kernel 5: batched-diagonal greedy scan + output write.
// For each 64-row word-batch w: lane w runs the serial 12-cyc/bit chain on
// cur[w] (diagonal row-words staged in double-buffered smem); surviving bits
// are broadcast and lanes w+1..15 OR-reduce the kept rows' later words from
// L2 (index chain is ALU-only -> loads pipeline). Exact reassociation of the
// sequential greedy update; bit-identical result.
// ---------------------------------------------------------------------------
__global__ __launch_bounds__(256)
void scan_kernel(float* __restrict__ out, int C) {
    __shared__ unsigned long long staging[128];    // double buffer 2x64
    __shared__ unsigned long long skeep[NWORDS];
    int c = blockIdx.x, tid = threadIdx.x;

    if (tid < 32) {
        const unsigned long long* __restrict__ mbase =
            g_mask + (size_t)c * KTOP * NWORDS;
        int lane = tid;
        unsigned long long curw =
            (lane < NWORDS) ? g_alive[c * NWORDS + lane] : 0ull;

        // stage word 0 diagonal rows
        {
            int r0 = lane, r1 = lane + 32;
            staging[lane]      = mbase[(size_t)r0 * NWORDS + 0];
            staging[lane + 32] = mbase[(size_t)r1 * NWORDS + 0];
        }
        __syncwarp();

        #pragma unroll
        for (int w = 0; w < NWORDS; w++) {
            int buf = (w & 1) << 6;
            // prefetch next batch's diagonal words into regs (overlaps serial phase)
            unsigned long long p0 = 0ull, p1 = 0ull;
            if (w + 1 < NWORDS) {
                int q0 = (w + 1) * 64 + lane, q1 = q0 + 32;
                p0 = (q0 < KTOP) ? mbase[(size_t)q0 * NWORDS + (w + 1)] : 0ull;
                p1 = (q1 < KTOP) ? mbase[(size_t)q1 * NWORDS + (w + 1)] : 0ull;
            }
            // serial 64-bit chain on lane w
            if (lane == w) {
                unsigned long long cw = curw;
                #pragma unroll 8
                for (int b = 0; b < 64; b++) {
                    unsigned long long m =
                        (unsigned long long)(((long long)(cw << (63 - b))) >> 63);
                    cw &= ~(staging[buf + b] & m);
                }
                curw = cw;
            }
            __syncwarp();
            unsigned long long kept = __shfl_sync(0xFFFFFFFFu, curw, w);
            // deferred updates to later words: OR over kept rows (MLP-friendly)
            if (lane > w && lane < NWORDS) {
                unsigned long long acc = 0ull, k = kept;
                while (k) {
                    int b = __ffsll((long long)k) - 1;
                    k &= k - 1;
                    acc |= mbase[(size_t)(w * 64 + b) * NWORDS + lane];
                }
                curw &= ~acc;
            }
            // publish prefetched staging for next batch
            int nbuf = buf ^ 64;
            staging[nbuf + lane]      = p0;
            staging[nbuf + lane + 32] = p1;
            __syncwarp();
        }
        if (lane < NWORDS) skeep[lane] = curw;
    }
    __syncthreads();

    float* out_scores = out;
    float* out_labels = out + (size_t)C * KTOP;
    float* out_boxes  = out + (size_t)2 * C * KTOP;
    float* out_keep   = out + (size_t)6 * C * KTOP;
    for (int i = tid; i < KTOP; i += 256) {
        bool kp = (skeep[i >> 6] >> (i & 63)) & 1ull;
        float kf = kp ? 1.0f : 0.0f;
        int o = c * KTOP + i;
        out_scores[o] = g_scoreK[o] * kf;
        out_labels[o] = (float)c;
        float4 bb = g_boxK[o];
        reinterpret_cast<float4*>(out_boxes)[o] =
            make_float4(bb.x * kf, bb.y * kf, bb.z * kf, bb.w * kf);
        out_keep[o] = kf;
    }
}

// ---------------------------------------------------------------------------
extern "C" void kernel_launch(void* const* d_in, const int* in_sizes, int n_in,
                              void* d_out, int out_size) {
    const float* cls  = (const float*)d_in[1];
    const float* reg  = (const float*)d_in[2];
    const float* anch = (const float*)d_in[3];

    int A = in_sizes[2] / 4;                    // 76725
    int C = in_sizes[1] / A;                    // 80
    int HW = in_sizes[0] / 3;                   // 640*640
    float H = floorf(sqrtf((float)HW) + 0.5f);  // 640

    decode_kernel<<<(A + 255) / 256, 256>>>(reg, anch, A, H, H);

    const int SEL_BLOCKS = 1184, SEL_THREADS = 320;
    long long gthreads = (long long)SEL_BLOCKS * SEL_THREADS;
    bool fast_ok = (C > 0) && ((C & 3) == 0) && (((A * (long long)C) & 3) == 0) &&
                   (((4 * gthreads) % C) == 0);
    if (fast_ok) {
        int astep = (int)((4 * gthreads) / C);
        select_kernel<<<SEL_BLOCKS, SEL_THREADS>>>(cls, A, C, astep);
    }
    sort_kernel<<<C, 1024>>>(cls, A, C);
    mask_kernel<<<dim3(C, NPH), 512>>>();
    scan_kernel<<<C, 256>>>((float*)d_out, C);
}

// round 10
// speedup vs baseline: 1.5091x; 1.5091x over previous
#include <cuda_runtime.h>
#include <math.h>

#define AMAX   76725
#define NCLS   80
#define KTOP   1000
#define KPAD   1024        // padded rows for scan smem (fixed-trip loops)
#define NCAND  2048
#define NWORDS 16
#define NBINS  8192
#define THR_SEL 0.98f
#define NPH    37          // mask row-phases: 80*37=2960 blocks = 5 exact waves @4/SM

__device__ float4              g_boxes[AMAX];
__device__ unsigned long long  g_cand[NCLS * NCAND];
__device__ int                 g_cnt[NCLS];
__device__ float               g_scoreK[NCLS * KTOP];
__device__ float4              g_boxK[NCLS * KTOP];
__device__ float               g_areaK[NCLS * KTOP];
__device__ unsigned long long  g_alive[NCLS * NWORDS];
__device__ unsigned long long  g_mask[NCLS * KTOP * NWORDS]; // words wb<i>>6 never written/read

// ---------------------------------------------------------------------------
__device__ __forceinline__ unsigned fkey(float s) {
    unsigned b = __float_as_uint(s);
    return (b & 0x80000000u) ? ~b : (b | 0x80000000u);
}
__device__ __forceinline__ float fkey_inv(unsigned k) {
    return __uint_as_float((k & 0x80000000u) ? (k & 0x7FFFFFFFu) : ~k);
}
__device__ __forceinline__ unsigned long long mkkey(float s, unsigned a) {
    return ((unsigned long long)fkey(s) << 32) |
           (unsigned long long)(0xFFFFFFFFu - a);
}

// ---------------------------------------------------------------------------
// Kernel 1: decode + clip all boxes; zero per-class counters.
// ---------------------------------------------------------------------------
__global__ void decode_kernel(const float* __restrict__ reg,
                              const float* __restrict__ anch,
                              int A, float W, float H) {
    int a = blockIdx.x * blockDim.x + threadIdx.x;
    if (a < NCLS) g_cnt[a] = 0;
    if (a >= A) return;
    float4 an = reinterpret_cast<const float4*>(anch)[a];
    float4 dl = reinterpret_cast<const float4*>(reg)[a];
    float aw = an.z - an.x;
    float ah = an.w - an.y;
    float cx = an.x + 0.5f * aw;
    float cy = an.y + 0.5f * ah;
    float pcx = cx + dl.x * 0.1f * aw;
    float pcy = cy + dl.y * 0.1f * ah;
    float pw = expf(dl.z * 0.2f) * aw;
    float ph = expf(dl.w * 0.2f) * ah;
    float4 b;
    b.x = fmaxf(pcx - 0.5f * pw, 0.0f);
    b.y = fmaxf(pcy - 0.5f * ph, 0.0f);
    b.z = fminf(pcx + 0.5f * pw, W);
    b.w = fminf(pcy + 0.5f * ph, H);
    g_boxes[a] = b;
}

// ---------------------------------------------------------------------------
// Kernel 2: coalesced single-pass candidate selection, fixed threshold.
// ---------------------------------------------------------------------------
__global__ __launch_bounds__(320)
void select_kernel(const float* __restrict__ cls, int A, int C, int astep) {
    int gthreads = gridDim.x * blockDim.x;
    int t = blockIdx.x * blockDim.x + threadIdx.x;
    int nf4 = (A * C) >> 2;
    const float4* cls4 = reinterpret_cast<const float4*>(cls);
    int e0 = t << 2;
    int a  = e0 / C;
    int c0 = e0 - a * C;
    for (int f = t; f < nf4; f += gthreads, a += astep) {
        float4 v = cls4[f];
        if (v.x > THR_SEL) {
            int p = atomicAdd(&g_cnt[c0 + 0], 1);
            if (p < NCAND) g_cand[(c0 + 0) * NCAND + p] = mkkey(v.x, (unsigned)a);
        }
        if (v.y > THR_SEL) {
            int p = atomicAdd(&g_cnt[c0 + 1], 1);
            if (p < NCAND) g_cand[(c0 + 1) * NCAND + p] = mkkey(v.y, (unsigned)a);
        }
        if (v.z > THR_SEL) {
            int p = atomicAdd(&g_cnt[c0 + 2], 1);
            if (p < NCAND) g_cand[(c0 + 2) * NCAND + p] = mkkey(v.z, (unsigned)a);
        }
        if (v.w > THR_SEL) {
            int p = atomicAdd(&g_cnt[c0 + 3], 1);
            if (p < NCAND) g_cand[(c0 + 3) * NCAND + p] = mkkey(v.w, (unsigned)a);
        }
    }
}

// ---------------------------------------------------------------------------
// Kernel 3: per-class sort (+embedded exact-reselect guard), extract top-K.
// ---------------------------------------------------------------------------
__global__ __launch_bounds__(1024)
void sort_kernel(const float* __restrict__ cls, int A, int C) {
    __shared__ unsigned long long buf[4096];       // 32 KB: cand = buf[0..2047]
    __shared__ unsigned long long salive[NWORDS];
    __shared__ int sT, sCnt;
    unsigned long long* cand = buf;
    unsigned*           hist = (unsigned*)buf;

    int c = blockIdx.x, tid = threadIdx.x;
    int n = g_cnt[c];
    bool bad = (n < KTOP) | (n > NCAND);

    if (!bad) {
        for (int i = tid; i < NCAND; i += 1024)
            cand[i] = (i < n) ? g_cand[c * NCAND + i] : 0ull;
        __syncthreads();
    } else {
        for (int i = tid; i < NBINS; i += 1024) hist[i] = 0u;
        if (tid == 0) sCnt = 0;
        __syncthreads();
        for (int a = tid; a < A; a += 1024) {
            float s = cls[a * C + c];
            int b = (int)(s * (float)NBINS);
            b = max(0, min(NBINS - 1, b));
            atomicAdd(&hist[b], 1u);
        }
        __syncthreads();
        if (tid == 0) {
            int cum = 0, t;
            for (t = NBINS - 1; t >= 0; t--) {
                cum += (int)hist[t];
                if (cum >= KTOP) break;
            }
            sT = (t < 0) ? 0 : t;
        }
        __syncthreads();
        int T = sT;
        unsigned long long keys[8]; int nk = 0;
        for (int a = tid; a < A; a += 1024) {
            float s = cls[a * C + c];
            int b = (int)(s * (float)NBINS);
            b = max(0, min(NBINS - 1, b));
            if (b >= T && nk < 8) keys[nk++] = mkkey(s, (unsigned)a);
        }
        __syncthreads();
        for (int q = 0; q < nk; q++) {
            int p = atomicAdd(&sCnt, 1);
            if (p < NCAND) cand[p] = keys[q];
        }
        __syncthreads();
        n = min(sCnt, NCAND);
        for (int i = tid; i < NCAND; i += 1024)
            if (i >= n) cand[i] = 0ull;
        __syncthreads();
    }

    for (int k = 2; k <= NCAND; k <<= 1) {
        for (int j = k >> 1; j > 0; j >>= 1) {
            #pragma unroll
            for (int rep = 0; rep < 2; rep++) {
                int i = tid + rep * 1024;
                int ixj = i ^ j;
                if (ixj > i) {
                    unsigned long long a0 = cand[i], b0 = cand[ixj];
                    bool desc = ((i & k) == 0);
                    bool swap = desc ? (a0 < b0) : (a0 > b0);
                    if (swap) { cand[i] = b0; cand[ixj] = a0; }
                }
            }
            __syncthreads();
        }
    }

    bool alive = false;
    {
        unsigned long long v = cand[min(tid, NCAND - 1)];
        float s = fkey_inv((unsigned)(v >> 32));
        unsigned a = 0xFFFFFFFFu - (unsigned)(v & 0xFFFFFFFFull);
        bool valid = (a < (unsigned)A);
        float4 bb = valid ? g_boxes[min(a, (unsigned)(AMAX - 1))]
                          : make_float4(0.f, 0.f, 0.f, 0.f);
        if (!valid) s = 0.f;
        if (tid < KTOP) {
            int o = c * KTOP + tid;
            g_scoreK[o] = s;
            g_boxK[o]   = bb;
            g_areaK[o]  = (bb.z - bb.x) * (bb.w - bb.y);
            alive = (s > 0.001f);
        }
    }
    unsigned bal = __ballot_sync(0xFFFFFFFFu, alive);
    if ((tid & 63) == 0 && tid < KTOP + 63)
        salive[tid >> 6] = (unsigned long long)bal;
    __syncthreads();
    if ((tid & 63) == 32 && tid < KTOP + 63)
        atomicOr(&salive[tid >> 6], (unsigned long long)bal << 32);
    __syncthreads();
    if (tid < NWORDS) g_alive[c * NWORDS + tid] = salive[tid];
}

// ---------------------------------------------------------------------------
// Kernel 4: IoU suppression bitmask. Smem-staged boxes (low regs), grid
// (C, 37): 2960 blocks = 5 exact waves @ 4 blocks/SM (forced by
// launch_bounds). IoU expressions token-identical to the passing kernel.
// ---------------------------------------------------------------------------
__global__ __launch_bounds__(512, 4)
void mask_kernel() {
    __shared__ float4 sbox[1024];
    __shared__ float  sarea[1024];
    int c = blockIdx.x, ph = blockIdx.y, tid = threadIdx.x;

    for (int i = tid; i < 1024; i += 512) {
        if (i < KTOP) {
            sbox[i]  = g_boxK[c * KTOP + i];
            sarea[i] = g_areaK[c * KTOP + i];
        } else {
            sbox[i]  = make_float4(3e8f, 3e8f, 3e8f, 3e8f);
            sarea[i] = 0.f;
        }
    }
    __syncthreads();

    int warp = tid >> 5, lane = tid & 31;
    int wb = warp;
    int j1 = wb * 64 + lane;
    int j2 = j1 + 32;
    float4 B1 = sbox[j1], B2 = sbox[j2];
    float ar1 = sarea[j1], ar2 = sarea[j2];

    int iLim = wb * 64 + 64;
    if (iLim > KTOP) iLim = KTOP;
    unsigned long long* mrow = g_mask + (size_t)c * KTOP * NWORDS + wb;

    for (int i0 = 2 * ph; i0 < iLim; i0 += 2 * NPH) {
        {
            int i = i0;
            float4 BI = sbox[i];
            float  ai = sarea[i];
            float xx1 = fmaxf(BI.x, B1.x), yy1 = fmaxf(BI.y, B1.y);
            float xx2 = fminf(BI.z, B1.z), yy2 = fminf(BI.w, B1.w);
            float inter = fmaxf(xx2 - xx1, 0.f) * fmaxf(yy2 - yy1, 0.f);
            bool p1 = (j1 > i) && (inter > 0.5f * (ai + ar1 - inter + 1e-8f));
            xx1 = fmaxf(BI.x, B2.x); yy1 = fmaxf(BI.y, B2.y);
            xx2 = fminf(BI.z, B2.z); yy2 = fminf(BI.w, B2.w);
            inter = fmaxf(xx2 - xx1, 0.f) * fmaxf(yy2 - yy1, 0.f);
            bool p2 = (j2 > i) && (inter > 0.5f * (ai + ar2 - inter + 1e-8f));
            unsigned m1 = __ballot_sync(0xFFFFFFFFu, p1);
            unsigned m2 = __ballot_sync(0xFFFFFFFFu, p2);
            if (lane == 0)
                mrow[(size_t)i * NWORDS] = ((unsigned long long)m2 << 32) | m1;
        }
        if (i0 + 1 < iLim) {
            int i = i0 + 1;
            float4 BI = sbox[i];
            float  ai = sarea[i];
            float xx1 = fmaxf(BI.x, B1.x), yy1 = fmaxf(BI.y, B1.y);
            float xx2 = fminf(BI.z, B1.z), yy2 = fminf(BI.w, B1.w);
            float inter = fmaxf(xx2 - xx1, 0.f) * fmaxf(yy2 - yy1, 0.f);
            bool p1 = (j1 > i) && (inter > 0.5f * (ai + ar1 - inter + 1e-8f));
            xx1 = fmaxf(BI.x, B2.x); yy1 = fmaxf(BI.y, B2.y);
            xx2 = fminf(BI.z, B2.z); yy2 = fminf(BI.w, B2.w);
            inter = fmaxf(xx2 - xx1, 0.f) * fmaxf(yy2 - yy1, 0.f);
            bool p2 = (j2 > i) && (inter > 0.5f * (ai + ar2 - inter + 1e-8f));
            unsigned m1 = __ballot_sync(0xFFFFFFFFu, p1);
            unsigned m2 = __ballot_sync(0xFFFFFFFFu, p2);
            if (lane == 0)
                mrow[(size_t)i * NWORDS] = ((unsigned long long)m2 << 32) | m1;
        }
    }
}

// ---------------------------------------------------------------------------
// Kernel 5: batched-diagonal greedy scan over SMEM + output write.
// Exact reassociation of the sequential greedy recurrence:
//   per 64-row word-batch w, lane w runs the serial bit chain on cur[w]
//   (later-word updates deferred); then surviving bits broadcast and lanes
//   w+1..15 OR-reduce kept rows' word-lane from smem (29-cyc LDS, loads
//   issued off the fast ffs chain -> pipelined). Bit-identical result.
// ---------------------------------------------------------------------------
#define SCAN_SMEM (KPAD * NWORDS * 8)          // 131072 B
__global__ __launch_bounds__(256)
void scan_kernel(float* __restrict__ out, int C) {
    extern __shared__ unsigned long long smask[];   // [KPAD][NWORDS]
    __shared__ unsigned long long skeep[NWORDS];
    int c = blockIdx.x, tid = threadIdx.x;

    const uint4* src = reinterpret_cast<const uint4*>(g_mask + (size_t)c * KTOP * NWORDS);
    uint4* dst = reinterpret_cast<uint4*>(smask);
    for (int i = tid; i < KTOP * NWORDS / 2; i += 256) dst[i] = src[i];
    for (int i = KTOP * NWORDS + tid; i < KPAD * NWORDS; i += 256) smask[i] = 0ull;
    __syncthreads();

    if (tid < 32) {
        int lane = tid;
        unsigned long long curw =
            (lane < NWORDS) ? g_alive[c * NWORDS + lane] : 0ull;

        #pragma unroll
        for (int w = 0; w < NWORDS; w++) {
            const int base = w * 64;
            // serial 64-bit chain on lane w (diag loads independent of chain)
            if (lane == w) {
                unsigned long long cw = curw;
                #pragma unroll 8
                for (int b = 0; b < 64; b++) {
                    unsigned long long row = smask[(base + b) * NWORDS + w];
                    unsigned long long m =
                        (unsigned long long)(((long long)(cw << (63 - b))) >> 63);
                    cw &= ~(row & m);
                }
                curw = cw;
            }
            __syncwarp();
            unsigned long long kept = __shfl_sync(0xFFFFFFFFu, curw, w);
            // deferred updates: uniform ffs loop over kept rows, smem loads
            if (lane < NWORDS) {
                unsigned long long acc = 0ull, k = kept;
                while (k) {
                    int b = __ffsll((long long)k) - 1;
                    k &= k - 1;
                    acc |= smask[(base + b) * NWORDS + lane];
                }
                if (lane > w) curw &= ~acc;
            }
            __syncwarp();
        }
        if (lane < NWORDS) skeep[lane] = curw;
    }
    __syncthreads();

    float* out_scores = out;
    float* out_labels = out + (size_t)C * KTOP;
    float* out_boxes  = out + (size_t)2 * C * KTOP;
    float* out_keep   = out + (size_t)6 * C * KTOP;
    for (int i = tid; i < KTOP; i += 256) {
        bool kp = (skeep[i >> 6] >> (i & 63)) & 1ull;
        float kf = kp ? 1.0f : 0.0f;
        int o = c * KTOP + i;
        out_scores[o] = g_scoreK[o] * kf;
        out_labels[o] = (float)c;
        float4 bb = g_boxK[o];
        reinterpret_cast<float4*>(out_boxes)[o] =
            make_float4(bb.x * kf, bb.y * kf, bb.z * kf, bb.w * kf);
        out_keep[o] = kf;
    }
}

// ---------------------------------------------------------------------------
extern "C" void kernel_launch(void* const* d_in, const int* in_sizes, int n_in,
                              void* d_out, int out_size) {
    const float* cls  = (const float*)d_in[1];
    const float* reg  = (const float*)d_in[2];
    const float* anch = (const float*)d_in[3];

    int A = in_sizes[2] / 4;                    // 76725
    int C = in_sizes[1] / A;                    // 80
    int HW = in_sizes[0] / 3;                   // 640*640
    float H = floorf(sqrtf((float)HW) + 0.5f);  // 640

    decode_kernel<<<(A + 255) / 256, 256>>>(reg, anch, A, H, H);

    const int SEL_BLOCKS = 1184, SEL_THREADS = 320;
    long long gthreads = (long long)SEL_BLOCKS * SEL_THREADS;
    bool fast_ok = (C > 0) && ((C & 3) == 0) && (((A * (long long)C) & 3) == 0) &&
                   (((4 * gthreads) % C) == 0);
    if (fast_ok) {
        int astep = (int)((4 * gthreads) / C);
        select_kernel<<<SEL_BLOCKS, SEL_THREADS>>>(cls, A, C, astep);
    }
    sort_kernel<<<C, 1024>>>(cls, A, C);
    mask_kernel<<<dim3(C, NPH), 512>>>();

    cudaFuncSetAttribute(scan_kernel,
                         cudaFuncAttributeMaxDynamicSharedMemorySize, SCAN_SMEM);
    scan_kernel<<<C, 256, SCAN_SMEM>>>((float*)d_out, C);
}

// round 12
// speedup vs baseline: 1.7772x; 1.1777x over previous
#include <cuda_runtime.h>
#include <math.h>

#define AMAX   76725
#define NCLS   80
#define KTOP   1000
#define NCAND  2048
#define NWORDS 16
#define NBINS  8192
#define THR_SEL 0.98f
#define NPH    37          // mask row-phases: 80*37=2960 blocks = 5 exact waves @4/SM

#define DEC_THREADS 320
#define DEC_BLOCKS  ((AMAX + DEC_THREADS - 1) / DEC_THREADS)   // 240
#define SEL_BLOCKS  1184

__device__ float4              g_boxes[AMAX];
__device__ unsigned long long  g_cand[NCLS * NCAND];
__device__ int                 g_cnt[NCLS];                    // zeroed at end of scan
__device__ float               g_scoreK[NCLS * KTOP];
__device__ float4              g_boxK[NCLS * KTOP];
__device__ float               g_areaK[NCLS * KTOP];
__device__ unsigned long long  g_alive[NCLS * NWORDS];
__device__ unsigned long long  g_mask[NCLS * KTOP * NWORDS];   // words wb<i>>6 never written/read

// ---------------------------------------------------------------------------
__device__ __forceinline__ unsigned fkey(float s) {
    unsigned b = __float_as_uint(s);
    return (b & 0x80000000u) ? ~b : (b | 0x80000000u);
}
__device__ __forceinline__ float fkey_inv(unsigned k) {
    return __uint_as_float((k & 0x80000000u) ? (k & 0x7FFFFFFFu) : ~k);
}
__device__ __forceinline__ unsigned long long mkkey(float s, unsigned a) {
    return ((unsigned long long)fkey(s) << 32) |
           (unsigned long long)(0xFFFFFFFFu - a);
}

// ---------------------------------------------------------------------------
// Kernel 1: fused decode (blocks [0, DEC_BLOCKS)) + select (rest).
// Independent work sets; no ordering hazard. g_cnt was zeroed by the
// previous replay's scan_kernel (or static zero-init on first run).
// ---------------------------------------------------------------------------
__global__ __launch_bounds__(DEC_THREADS)
void decode_select_kernel(const float* __restrict__ reg,
                          const float* __restrict__ anch,
                          const float* __restrict__ cls,
                          int A, int C, float W, float H, int astep) {
    if (blockIdx.x < DEC_BLOCKS) {
        int a = blockIdx.x * DEC_THREADS + threadIdx.x;
        if (a >= A) return;
        float4 an = reinterpret_cast<const float4*>(anch)[a];
        float4 dl = reinterpret_cast<const float4*>(reg)[a];
        float aw = an.z - an.x;
        float ah = an.w - an.y;
        float cx = an.x + 0.5f * aw;
        float cy = an.y + 0.5f * ah;
        float pcx = cx + dl.x * 0.1f * aw;
        float pcy = cy + dl.y * 0.1f * ah;
        float pw = expf(dl.z * 0.2f) * aw;
        float ph = expf(dl.w * 0.2f) * ah;
        float4 b;
        b.x = fmaxf(pcx - 0.5f * pw, 0.0f);
        b.y = fmaxf(pcy - 0.5f * ph, 0.0f);
        b.z = fminf(pcx + 0.5f * pw, W);
        b.w = fminf(pcy + 0.5f * ph, H);
        g_boxes[a] = b;
        return;
    }
    // ---- select part ----
    int gthreads = SEL_BLOCKS * DEC_THREADS;
    int t = (blockIdx.x - DEC_BLOCKS) * DEC_THREADS + threadIdx.x;
    int nf4 = (A * C) >> 2;
    const float4* cls4 = reinterpret_cast<const float4*>(cls);
    int e0 = t << 2;
    int a  = e0 / C;
    int c0 = e0 - a * C;      // constant per thread across iterations
    for (int f = t; f < nf4; f += gthreads, a += astep) {
        float4 v = cls4[f];
        if (v.x > THR_SEL) {
            int p = atomicAdd(&g_cnt[c0 + 0], 1);
            if (p < NCAND) g_cand[(c0 + 0) * NCAND + p] = mkkey(v.x, (unsigned)a);
        }
        if (v.y > THR_SEL) {
            int p = atomicAdd(&g_cnt[c0 + 1], 1);
            if (p < NCAND) g_cand[(c0 + 1) * NCAND + p] = mkkey(v.y, (unsigned)a);
        }
        if (v.z > THR_SEL) {
            int p = atomicAdd(&g_cnt[c0 + 2], 1);
            if (p < NCAND) g_cand[(c0 + 2) * NCAND + p] = mkkey(v.z, (unsigned)a);
        }
        if (v.w > THR_SEL) {
            int p = atomicAdd(&g_cnt[c0 + 3], 1);
            if (p < NCAND) g_cand[(c0 + 3) * NCAND + p] = mkkey(v.w, (unsigned)a);
        }
    }
}

// ---------------------------------------------------------------------------
// Kernel 2: per-class sort (+embedded exact-reselect guard), extract top-K.
// ---------------------------------------------------------------------------
__global__ __launch_bounds__(1024)
void sort_kernel(const float* __restrict__ cls, int A, int C) {
    __shared__ unsigned long long buf[4096];       // 32 KB: cand = buf[0..2047]
    __shared__ unsigned long long salive[NWORDS];
    __shared__ int sT, sCnt;
    unsigned long long* cand = buf;
    unsigned*           hist = (unsigned*)buf;

    int c = blockIdx.x, tid = threadIdx.x;
    int n = g_cnt[c];
    bool bad = (n < KTOP) | (n > NCAND);

    if (!bad) {
        for (int i = tid; i < NCAND; i += 1024)
            cand[i] = (i < n) ? g_cand[c * NCAND + i] : 0ull;
        __syncthreads();
    } else {
        for (int i = tid; i < NBINS; i += 1024) hist[i] = 0u;
        if (tid == 0) sCnt = 0;
        __syncthreads();
        for (int a = tid; a < A; a += 1024) {
            float s = cls[a * C + c];
            int b = (int)(s * (float)NBINS);
            b = max(0, min(NBINS - 1, b));
            atomicAdd(&hist[b], 1u);
        }
        __syncthreads();
        if (tid == 0) {
            int cum = 0, t;
            for (t = NBINS - 1; t >= 0; t--) {
                cum += (int)hist[t];
                if (cum >= KTOP) break;
            }
            sT = (t < 0) ? 0 : t;
        }
        __syncthreads();
        int T = sT;
        unsigned long long keys[8]; int nk = 0;
        for (int a = tid; a < A; a += 1024) {
            float s = cls[a * C + c];
            int b = (int)(s * (float)NBINS);
            b = max(0, min(NBINS - 1, b));
            if (b >= T && nk < 8) keys[nk++] = mkkey(s, (unsigned)a);
        }
        __syncthreads();
        for (int q = 0; q < nk; q++) {
            int p = atomicAdd(&sCnt, 1);
            if (p < NCAND) cand[p] = keys[q];
        }
        __syncthreads();
        n = min(sCnt, NCAND);
        for (int i = tid; i < NCAND; i += 1024)
            if (i >= n) cand[i] = 0ull;
        __syncthreads();
    }

    for (int k = 2; k <= NCAND; k <<= 1) {
        for (int j = k >> 1; j > 0; j >>= 1) {
            #pragma unroll
            for (int rep = 0; rep < 2; rep++) {
                int i = tid + rep * 1024;
                int ixj = i ^ j;
                if (ixj > i) {
                    unsigned long long a0 = cand[i], b0 = cand[ixj];
                    bool desc = ((i & k) == 0);
                    bool swap = desc ? (a0 < b0) : (a0 > b0);
                    if (swap) { cand[i] = b0; cand[ixj] = a0; }
                }
            }
            __syncthreads();
        }
    }

    bool alive = false;
    {
        unsigned long long v = cand[min(tid, NCAND - 1)];
        float s = fkey_inv((unsigned)(v >> 32));
        unsigned a = 0xFFFFFFFFu - (unsigned)(v & 0xFFFFFFFFull);
        bool valid = (a < (unsigned)A);
        float4 bb = valid ? g_boxes[min(a, (unsigned)(AMAX - 1))]
                          : make_float4(0.f, 0.f, 0.f, 0.f);
        if (!valid) s = 0.f;
        if (tid < KTOP) {
            int o = c * KTOP + tid;
            g_scoreK[o] = s;
            g_boxK[o]   = bb;
            g_areaK[o]  = (bb.z - bb.x) * (bb.w - bb.y);
            alive = (s > 0.001f);
        }
    }
    unsigned bal = __ballot_sync(0xFFFFFFFFu, alive);
    if ((tid & 63) == 0 && tid < KTOP + 63)
        salive[tid >> 6] = (unsigned long long)bal;
    __syncthreads();
    if ((tid & 63) == 32 && tid < KTOP + 63)
        atomicOr(&salive[tid >> 6], (unsigned long long)bal << 32);
    __syncthreads();
    if (tid < NWORDS) g_alive[c * NWORDS + tid] = salive[tid];
}

// ---------------------------------------------------------------------------
// Kernel 3: IoU suppression bitmask. Smem-staged boxes (31 regs), grid
// (C, NPH) = 2960 blocks = 5 exact waves @ 4 blocks/SM. IoU expressions
// token-identical to the passing kernels.
// ---------------------------------------------------------------------------
__global__ __launch_bounds__(512, 4)
void mask_kernel() {
    __shared__ float4 sbox[1024];
    __shared__ float  sarea[1024];
    int c = blockIdx.x, ph = blockIdx.y, tid = threadIdx.x;

    for (int i = tid; i < 1024; i += 512) {
        if (i < KTOP) {
            sbox[i]  = g_boxK[c * KTOP + i];
            sarea[i] = g_areaK[c * KTOP + i];
        } else {
            sbox[i]  = make_float4(3e8f, 3e8f, 3e8f, 3e8f);
            sarea[i] = 0.f;
        }
    }
    __syncthreads();

    int warp = tid >> 5, lane = tid & 31;
    int wb = warp;
    int j1 = wb * 64 + lane;
    int j2 = j1 + 32;
    float4 B1 = sbox[j1], B2 = sbox[j2];
    float ar1 = sarea[j1], ar2 = sarea[j2];

    int iLim = wb * 64 + 64;
    if (iLim > KTOP) iLim = KTOP;
    unsigned long long* mrow = g_mask + (size_t)c * KTOP * NWORDS + wb;

    for (int i0 = 2 * ph; i0 < iLim; i0 += 2 * NPH) {
        {
            int i = i0;
            float4 BI = sbox[i];
            float  ai = sarea[i];
            float xx1 = fmaxf(BI.x, B1.x), yy1 = fmaxf(BI.y, B1.y);
            float xx2 = fminf(BI.z, B1.z), yy2 = fminf(BI.w, B1.w);
            float inter = fmaxf(xx2 - xx1, 0.f) * fmaxf(yy2 - yy1, 0.f);
            bool p1 = (j1 > i) && (inter > 0.5f * (ai + ar1 - inter + 1e-8f));
            xx1 = fmaxf(BI.x, B2.x); yy1 = fmaxf(BI.y, B2.y);
            xx2 = fminf(BI.z, B2.z); yy2 = fminf(BI.w, B2.w);
            inter = fmaxf(xx2 - xx1, 0.f) * fmaxf(yy2 - yy1, 0.f);
            bool p2 = (j2 > i) && (inter > 0.5f * (ai + ar2 - inter + 1e-8f));
            unsigned m1 = __ballot_sync(0xFFFFFFFFu, p1);
            unsigned m2 = __ballot_sync(0xFFFFFFFFu, p2);
            if (lane == 0)
                mrow[(size_t)i * NWORDS] = ((unsigned long long)m2 << 32) | m1;
        }
        if (i0 + 1 < iLim) {
            int i = i0 + 1;
            float4 BI = sbox[i];
            float  ai = sarea[i];
            float xx1 = fmaxf(BI.x, B1.x), yy1 = fmaxf(BI.y, B1.y);
            float xx2 = fminf(BI.z, B1.z), yy2 = fminf(BI.w, B1.w);
            float inter = fmaxf(xx2 - xx1, 0.f) * fmaxf(yy2 - yy1, 0.f);
            bool p1 = (j1 > i) && (inter > 0.5f * (ai + ar1 - inter + 1e-8f));
            xx1 = fmaxf(BI.x, B2.x); yy1 = fmaxf(BI.y, B2.y);
            xx2 = fminf(BI.z, B2.z); yy2 = fminf(BI.w, B2.w);
            inter = fmaxf(xx2 - xx1, 0.f) * fmaxf(yy2 - yy1, 0.f);
            bool p2 = (j2 > i) && (inter > 0.5f * (ai + ar2 - inter + 1e-8f));
            unsigned m1 = __ballot_sync(0xFFFFFFFFu, p1);
            unsigned m2 = __ballot_sync(0xFFFFFFFFu, p2);
            if (lane == 0)
                mrow[(size_t)i * NWORDS] = ((unsigned long long)m2 << 32) | m1;
        }
    }
}

// ---------------------------------------------------------------------------
// Kernel 4: serial greedy scan (single thread, LOP3-dense, proven in the
// 171.7us config) + output write + g_cnt reset for next replay.
// ---------------------------------------------------------------------------
#define SCAN_SMEM (KTOP * NWORDS * 8)
__global__ __launch_bounds__(256)
void scan_kernel(float* __restrict__ out, int C) {
    extern __shared__ unsigned long long smask[];
    __shared__ unsigned long long skeep[NWORDS];
    int c = blockIdx.x, tid = threadIdx.x;

    const uint4* src = reinterpret_cast<const uint4*>(g_mask + (size_t)c * KTOP * NWORDS);
    uint4* dst = reinterpret_cast<uint4*>(smask);
    for (int i = tid; i < KTOP * NWORDS / 2; i += 256) dst[i] = src[i];
    __syncthreads();

    if (tid == 0) {
        unsigned long long cur[NWORDS];
        #pragma unroll
        for (int w = 0; w < NWORDS; w++) cur[w] = g_alive[c * NWORDS + w];

        #pragma unroll
        for (int w = 0; w < NWORDS; w++) {
            const int bmax = (KTOP - w * 64 < 64) ? (KTOP - w * 64) : 64;
            const ulonglong2* rbase =
                reinterpret_cast<const ulonglong2*>(smask + (w * 64) * NWORDS);
            #pragma unroll 4
            for (int b = 0; b < bmax; b++) {
                unsigned long long m =
                    (unsigned long long)(((long long)(cur[w] << (63 - b))) >> 63);
                const ulonglong2* row2 = rbase + b * (NWORDS / 2);
                #pragma unroll
                for (int p = (w >> 1); p < 8; p++) {
                    ulonglong2 r = row2[p];        // words < w are zero: harmless
                    cur[2 * p]     &= ~(r.x & m);  // single LOP3 per word
                    cur[2 * p + 1] &= ~(r.y & m);
                }
            }
        }
        #pragma unroll
        for (int w = 0; w < NWORDS; w++) skeep[w] = cur[w];
        g_cnt[c] = 0;                               // reset for next replay
    }
    __syncthreads();

    float* out_scores = out;
    float* out_labels = out + (size_t)C * KTOP;
    float* out_boxes  = out + (size_t)2 * C * KTOP;
    float* out_keep   = out + (size_t)6 * C * KTOP;
    for (int i = tid; i < KTOP; i += 256) {
        bool kp = (skeep[i >> 6] >> (i & 63)) & 1ull;
        float kf = kp ? 1.0f : 0.0f;
        int o = c * KTOP + i;
        out_scores[o] = g_scoreK[o] * kf;
        out_labels[o] = (float)c;
        float4 bb = g_boxK[o];
        reinterpret_cast<float4*>(out_boxes)[o] =
            make_float4(bb.x * kf, bb.y * kf, bb.z * kf, bb.w * kf);
        out_keep[o] = kf;
    }
}

// ---------------------------------------------------------------------------
extern "C" void kernel_launch(void* const* d_in, const int* in_sizes, int n_in,
                              void* d_out, int out_size) {
    const float* cls  = (const float*)d_in[1];
    const float* reg  = (const float*)d_in[2];
    const float* anch = (const float*)d_in[3];

    int A = in_sizes[2] / 4;                    // 76725
    int C = in_sizes[1] / A;                    // 80
    int HW = in_sizes[0] / 3;                   // 640*640
    float H = floorf(sqrtf((float)HW) + 0.5f);  // 640

    long long gthreads = (long long)SEL_BLOCKS * DEC_THREADS;
    bool fast_ok = (C > 0) && ((C & 3) == 0) && (((A * (long long)C) & 3) == 0) &&
                   (((4 * gthreads) % C) == 0);
    int astep = fast_ok ? (int)((4 * gthreads) / C) : 0;
    int nblocks = DEC_BLOCKS + (fast_ok ? SEL_BLOCKS : 0);

    decode_select_kernel<<<nblocks, DEC_THREADS>>>(reg, anch, cls, A, C, H, H, astep);
    sort_kernel<<<C, 1024>>>(cls, A, C);
    mask_kernel<<<dim3(C, NPH), 512>>>();

    cudaFuncSetAttribute(scan_kernel,
                         cudaFuncAttributeMaxDynamicSharedMemorySize, SCAN_SMEM);
    scan_kernel<<<C, 256, SCAN_SMEM>>>((float*)d_out, C);
}